// round 1
// baseline (speedup 1.0000x reference)
#include <cuda_runtime.h>
#include <cstddef>

// ---------------- problem constants ----------------
#define T_DIM   32
#define N_DIM   512
#define K_DIM   262144        // 1*64*4096
#define THRESH  0.2f
#define KWTA    8

// ---------------- GEMM tiling ----------------
#define TILE_N  256           // output features per block (2 n-tiles)
#define BK      16            // k per smem stage
#define KSPLIT  74            // k-chunks -> 2*74 = 148 blocks = 1/SM
#define CHUNK   3552          // ceil(262144/74) rounded to mult of 32; last chunk = 2848

// smem layout (floats), static (<48KB)
#define WS_PITCH 18           // 16 data + 2 pad; odd in 8B units -> conflict-free LDS.64
#define XS_PITCH 20           // 16 data + 4 pad; row pitch 80B -> 16B aligned for LDS.128
#define WS_STAGE (TILE_N * WS_PITCH)            // 4608
#define XS_BASE  (2 * WS_STAGE)                 // 9216
#define XS_STAGE (T_DIM * XS_PITCH)             // 640
#define SMEM_FLOATS (XS_BASE + 2 * XS_STAGE)    // 10496 -> 41984 B

// ---------------- device scratch ----------------
__device__ float g_part[KSPLIT * T_DIM * N_DIM];  // ~4.85 MB
__device__ float g_pot[T_DIM * N_DIM];

// ---------------- helpers ----------------
__device__ __forceinline__ unsigned long long pk64(float a, float b) {
    unsigned long long r;
    asm("mov.b64 %0, {%1, %2};" : "=l"(r) : "f"(a), "f"(b));
    return r;
}
__device__ __forceinline__ void upk64(unsigned long long u, float& a, float& b) {
    asm("mov.b64 {%0, %1}, %2;" : "=f"(a), "=f"(b) : "l"(u));
}
#define FMA2(acc, a, b) asm("fma.rn.f32x2 %0, %1, %2, %0;" : "+l"(acc) : "l"(a), "l"(b))

__device__ __forceinline__ unsigned int smem_u32(const void* p) {
    return (unsigned int)__cvta_generic_to_shared(p);
}
__device__ __forceinline__ void cp8(unsigned int dst, const void* src) {
    asm volatile("cp.async.ca.shared.global [%0], [%1], 8;" :: "r"(dst), "l"(src));
}
__device__ __forceinline__ void cp16(unsigned int dst, const void* src) {
    asm volatile("cp.async.cg.shared.global [%0], [%1], 16;" :: "r"(dst), "l"(src));
}

// ---------------- kernel 1: K-split fp32 GEMM (f32x2 FMAs) ----------------
// grid: (KSPLIT, N_DIM/TILE_N), block: 256 threads
// thread tile: TM=8 t's x TN=4 o's, accumulators are f32x2 over (k even, k odd)
__global__ void __launch_bounds__(256)
gemm_kernel(const float* __restrict__ x, const float* __restrict__ w) {
    __shared__ float smem[SMEM_FLOATS];

    const int tid = threadIdx.x;
    const int kc  = blockIdx.x;
    const int nb  = blockIdx.y;
    const int k0  = kc * CHUNK;
    const int klen = (K_DIM - k0 < CHUNK) ? (K_DIM - k0) : CHUNK;   // multiple of 32
    const int nstage = klen / BK;
    const int o_base = nb * TILE_N;

    const int tx = tid & 63;   // 64 o-groups, o = o_base + tx + 64*j
    const int ty = tid >> 6;   // 4 t-groups, t = ty*8 + i

    auto load_stage = [&](int buf, int kpos) {
        float* ws = smem + buf * WS_STAGE;
        float* xs = smem + XS_BASE + buf * XS_STAGE;
        // weight tile: 256 rows x 16 floats = 2048 x 8B chunks, 8 per thread
        #pragma unroll
        for (int i = 0; i < 8; ++i) {
            int id  = i * 256 + tid;
            int row = id >> 3;
            int c8  = id & 7;
            cp8(smem_u32(ws + row * WS_PITCH + c8 * 2),
                w + (size_t)(o_base + row) * K_DIM + kpos + c8 * 2);
        }
        // x tile: 32 rows x 16 floats = 128 x 16B chunks (threads 0..127)
        if (tid < 128) {
            int row = tid >> 2;
            int c16 = tid & 3;
            cp16(smem_u32(xs + row * XS_PITCH + c16 * 4),
                 x + (size_t)row * K_DIM + kpos + c16 * 4);
        }
        asm volatile("cp.async.commit_group;");
    };

    unsigned long long acc[8][4];
    #pragma unroll
    for (int i = 0; i < 8; ++i)
        #pragma unroll
        for (int j = 0; j < 4; ++j) acc[i][j] = 0ULL;

    load_stage(0, k0);

    for (int s = 0; s < nstage; ++s) {
        asm volatile("cp.async.wait_group 0;");
        __syncthreads();
        if (s + 1 < nstage) load_stage((s + 1) & 1, k0 + (s + 1) * BK);

        const float* ws = smem + (s & 1) * WS_STAGE;
        const float* xs = smem + XS_BASE + (s & 1) * XS_STAGE;

        #pragma unroll
        for (int c = 0; c < 4; ++c) {        // 4 x (2 k-pairs) = 16 k
            unsigned long long xa[8], xb[8];
            #pragma unroll
            for (int i = 0; i < 8; ++i) {
                float4 v = *(const float4*)(xs + (ty * 8 + i) * XS_PITCH + c * 4);
                xa[i] = pk64(v.x, v.y);
                xb[i] = pk64(v.z, v.w);
            }
            unsigned long long wv[4];
            #pragma unroll
            for (int j = 0; j < 4; ++j)
                wv[j] = *(const unsigned long long*)(ws + (tx + 64 * j) * WS_PITCH + c * 4);
            #pragma unroll
            for (int i = 0; i < 8; ++i)
                #pragma unroll
                for (int j = 0; j < 4; ++j)
                    FMA2(acc[i][j], xa[i], wv[j]);
            #pragma unroll
            for (int j = 0; j < 4; ++j)
                wv[j] = *(const unsigned long long*)(ws + (tx + 64 * j) * WS_PITCH + c * 4 + 2);
            #pragma unroll
            for (int i = 0; i < 8; ++i)
                #pragma unroll
                for (int j = 0; j < 4; ++j)
                    FMA2(acc[i][j], xb[i], wv[j]);
        }
    }

    // epilogue: fold (even,odd) lanes, write partials
    #pragma unroll
    for (int i = 0; i < 8; ++i) {
        int t = ty * 8 + i;
        #pragma unroll
        for (int j = 0; j < 4; ++j) {
            float lo, hi;
            upk64(acc[i][j], lo, hi);
            int o = o_base + tx + 64 * j;
            g_part[(size_t)kc * (T_DIM * N_DIM) + t * N_DIM + o] = lo + hi;
        }
    }
}

// ---------------- kernel 2: K-split reduce + threshold ----------------
__global__ void reduce_pot_kernel() {
    int idx = blockIdx.x * 256 + threadIdx.x;   // < 16384
    float s = 0.f;
    for (int kc = 0; kc < KSPLIT; ++kc)
        s += g_part[(size_t)kc * (T_DIM * N_DIM) + idx];
    g_pot[idx] = (s < THRESH) ? 0.f : s;
}

// ---------------- kernel 3: spikes / k-WTA / output ----------------
// Replicates: first = clip(T - count, 0, T-1); value = pot[first];
// v = max(spike*value) * T; total = sum_t spike*(value+v);
// 8x argmax (first-index tie-break), zeroing winners; out = spikes masked by winners.
__global__ void __launch_bounds__(512) winners_kernel(float* __restrict__ out) {
    __shared__ float s_total[N_DIM];
    __shared__ int   s_sel[N_DIM];
    __shared__ float s_red[N_DIM];

    const int o = threadIdx.x;

    float p[T_DIM];
    int count = 0;
    #pragma unroll
    for (int t = 0; t < T_DIM; ++t) {
        p[t] = g_pot[t * N_DIM + o];
        count += (p[t] != 0.f) ? 1 : 0;
    }
    int first = T_DIM - count;                // >= 0
    if (first > T_DIM - 1) first = T_DIM - 1; // clip upper
    float value = p[first];
    float m = (count > 0) ? value : 0.f;

    // block max-reduce for v
    s_red[o] = m;
    __syncthreads();
    #pragma unroll
    for (int st = 256; st > 0; st >>= 1) {
        if (o < st) s_red[o] = fmaxf(s_red[o], s_red[o + st]);
        __syncthreads();
    }
    float v  = s_red[0] * (float)T_DIM;
    float vv = value + v;

    float total = 0.f;
    #pragma unroll
    for (int t = 0; t < T_DIM; ++t)
        if (p[t] != 0.f) total += vv;

    s_total[o] = total;
    s_sel[o]   = 0;
    __syncthreads();

    if (o == 0) {
        for (int it = 0; it < KWTA; ++it) {
            int bi = 0;
            float bv = s_total[0];
            for (int j = 1; j < N_DIM; ++j)
                if (s_total[j] > bv) { bv = s_total[j]; bi = j; }  // first max wins
            if (bv != 0.f) s_sel[bi] = 1;
            s_total[bi] = 0.f;
        }
    }
    __syncthreads();

    int sel = s_sel[o];
    #pragma unroll
    for (int t = 0; t < T_DIM; ++t)
        out[t * N_DIM + o] = (sel && p[t] != 0.f) ? 1.f : 0.f;
}

// ---------------- launch ----------------
extern "C" void kernel_launch(void* const* d_in, const int* in_sizes, int n_in,
                              void* d_out, int out_size) {
    const float* a = (const float*)d_in[0];
    const float* b = (const float*)d_in[1];
    // identify inputs by element count (robust to metadata order)
    const float* x;  // rec_field: 32*262144 = 8388608
    const float* w;  // weight:   512*262144 = 134217728
    if (in_sizes[0] == T_DIM * K_DIM) { x = a; w = b; }
    else                              { x = b; w = a; }

    float* out = (float*)d_out;

    dim3 grid(KSPLIT, N_DIM / TILE_N);   // (74, 2) = 148 blocks
    gemm_kernel<<<grid, 256>>>(x, w);
    reduce_pot_kernel<<<(T_DIM * N_DIM) / 256, 256>>>();
    winners_kernel<<<1, N_DIM>>>(out);
}